// round 13
// baseline (speedup 1.0000x reference)
#include <cuda_runtime.h>
#include <cuda_bf16.h>
#include <cuda_fp16.h>
#include <cstdint>

// ---------------------------------------------------------------------------
// GAT 2-layer forward, round 13 (round-10 skeleton, h1 back to fp32):
//   - prep: zero counters + W1 fp16 transpose
//   - bucketed counting sort of edges by dst (int4-vectorized)
//   - GEMM1: fp16 mma.sync m16n8k16 (fp32 accum), 1-sync pipeline; att1 fused;
//     h1 -> fp32 (agg1 is issue-bound: fp32 kills 8 cvts/edge/lane)
//   - agg1: WARP per node; lane owns 8 features (2x float4 gathers); ELU;
//     hE -> fp16
//   - gemm2: warp per node (hE fp16 @ W2) + fused a_s2/a_d2
//   - agg2: 16 lanes per node -> out
// ---------------------------------------------------------------------------

#define NMAX 20000
#define EMAX 320000
#define CAP  128

__device__ int   g_cnt[NMAX];
__device__ int2  g_edge[NMAX * CAP];
__device__ __half g_Bf[256 * 256];            // W1^T fp16, [N=256][K=256]
__device__ float g_h1[(size_t)NMAX * 256];    // h1 fp32
__device__ __half g_hEh[(size_t)NMAX * 256];  // hE fp16
__device__ float g_as1[NMAX * 8];
__device__ float g_ad1[NMAX * 8];
__device__ float g_h2[NMAX * 16];
__device__ float g_as2[NMAX];
__device__ float g_ad2[NMAX];

// ------------------------------ helpers ------------------------------------
__device__ __forceinline__ uint32_t smem_u32(const void* p) {
    uint32_t a;
    asm("{ .reg .u64 t; cvta.to.shared.u64 t, %1; cvt.u32.u64 %0, t; }"
        : "=r"(a) : "l"(p));
    return a;
}
__device__ __forceinline__ void ldm_x4(uint32_t& r0, uint32_t& r1,
                                       uint32_t& r2, uint32_t& r3, uint32_t a) {
    asm volatile("ldmatrix.sync.aligned.m8n8.x4.shared.b16 {%0,%1,%2,%3}, [%4];"
                 : "=r"(r0), "=r"(r1), "=r"(r2), "=r"(r3) : "r"(a));
}
__device__ __forceinline__ void ldm_x2(uint32_t& r0, uint32_t& r1, uint32_t a) {
    asm volatile("ldmatrix.sync.aligned.m8n8.x2.shared.b16 {%0,%1}, [%2];"
                 : "=r"(r0), "=r"(r1) : "r"(a));
}
__device__ __forceinline__ void mma16816f(float* c, uint32_t a0, uint32_t a1,
                                          uint32_t a2, uint32_t a3,
                                          uint32_t b0, uint32_t b1) {
    asm volatile(
        "mma.sync.aligned.m16n8k16.row.col.f32.f16.f16.f32 "
        "{%0,%1,%2,%3},{%4,%5,%6,%7},{%8,%9},{%0,%1,%2,%3};"
        : "+f"(c[0]), "+f"(c[1]), "+f"(c[2]), "+f"(c[3])
        : "r"(a0), "r"(a1), "r"(a2), "r"(a3), "r"(b0), "r"(b1));
}
#define CP16(dst, src) \
    asm volatile("cp.async.cg.shared.global [%0], [%1], 16;" :: "r"(dst), "l"(src))
#define CP_COMMIT() asm volatile("cp.async.commit_group;")

// ------------------------------ prep: zero + W1 fp16 -----------------------
__global__ void prep_k(const float* __restrict__ W1, int N) {
    int i = blockIdx.x * blockDim.x + threadIdx.x;
    if (i < 65536) {
        int k = i >> 8, n = i & 255;      // W1 is [K=256][N=256]
        g_Bf[n * 256 + k] = __float2half_rn(W1[i]);
    }
    if (i < N) g_cnt[i] = 0;
}

// ------------------------------ scatter (buckets) --------------------------
__global__ void scatter_k(const int* __restrict__ ei, const float* __restrict__ ew,
                          int E, int ET) {
    int idx = blockIdx.x * blockDim.x + threadIdx.x;
    int i0 = idx * 4;
    if (i0 >= ET) return;
    if (i0 + 3 < E) {
        int4   s4 = ((const int4*)ei)[idx];
        int4   d4 = ((const int4*)(ei + E))[idx];
        float4 w4 = ((const float4*)ew)[idx];
        int r;
        r = atomicAdd(&g_cnt[d4.x], 1);
        if (r < CAP) g_edge[d4.x * CAP + r] = make_int2(s4.x, __float_as_int(w4.x));
        r = atomicAdd(&g_cnt[d4.y], 1);
        if (r < CAP) g_edge[d4.y * CAP + r] = make_int2(s4.y, __float_as_int(w4.y));
        r = atomicAdd(&g_cnt[d4.z], 1);
        if (r < CAP) g_edge[d4.z * CAP + r] = make_int2(s4.z, __float_as_int(w4.z));
        r = atomicAdd(&g_cnt[d4.w], 1);
        if (r < CAP) g_edge[d4.w * CAP + r] = make_int2(s4.w, __float_as_int(w4.w));
    } else {
#pragma unroll
        for (int u = 0; u < 4; u++) {
            int i = i0 + u;
            if (i >= ET) break;
            int src, dst; float w;
            if (i < E) { src = ei[i]; dst = ei[E + i]; w = ew[i]; }
            else       { src = i - E; dst = i - E;     w = 1.0f; }
            int r = atomicAdd(&g_cnt[dst], 1);
            if (r < CAP) g_edge[dst * CAP + r] = make_int2(src, __float_as_int(w));
        }
    }
}

// ------------------------------ GEMM1 (fp16 HMMA, 1-sync pipeline) ---------
#define ASTR 40
#define TILEB 10240
#define STG  (2 * TILEB)
#define OFF_A 0
#define OFF_B TILEB
#define G1_SMEM (2 * STG)     // 40960

__global__ void __launch_bounds__(256, 2)
gemm1_mma(const float* __restrict__ x, const float* __restrict__ attS,
          const float* __restrict__ attD, int M) {
    extern __shared__ char dsm[];
    uint32_t sb = smem_u32(dsm);

    int tid = threadIdx.x, lane = tid & 31, wid = tid >> 5;
    int warp_m = wid & 1, warp_n = wid >> 1;
    int row0 = blockIdx.x * 128;
    int col0 = blockIdx.y * 128;

    float acc[4][4][4];
#pragma unroll
    for (int a = 0; a < 4; a++)
#pragma unroll
        for (int b = 0; b < 4; b++)
#pragma unroll
            for (int c = 0; c < 4; c++) acc[a][b][c] = 0.f;

    int lrow = tid >> 1, lhalf = (tid & 1) * 16;
    int grow = row0 + lrow;
    bool rv = grow < M;
    const char* b_src = (const char*)&g_Bf[(col0 + lrow) * 256 + lhalf];
    uint32_t doff = (uint32_t)((lrow * ASTR + lhalf) * 2);

    int a_r = warp_m * 64 + (lane & 15);
    int a_c8 = (lane >> 4) * 8;
    int b_r = warp_n * 32 + (lane & 7);
    int b_c8 = ((lane >> 3) & 1) * 8;

#define ISSUE_B(stage, ks) do {                                            \
        uint32_t _b = sb + (uint32_t)(stage) * STG;                        \
        int _kb = (ks) * 64;                                               \
        CP16(_b + OFF_B + doff,      b_src + _kb);                         \
        CP16(_b + OFF_B + doff + 16, b_src + _kb + 16);                    \
        CP_COMMIT();                                                       \
    } while (0)

    float4 av[4];
#pragma unroll
    for (int j = 0; j < 4; j++)
        av[j] = rv ? *(const float4*)&x[(size_t)grow * 256 + lhalf + j * 4]
                   : make_float4(0.f, 0.f, 0.f, 0.f);
    ISSUE_B(0, 0);

    for (int ks = 0; ks < 8; ks++) {
        int stage = ks & 1;
        uint32_t base = sb + (uint32_t)stage * STG;

        char* asm_base = dsm + (size_t)stage * STG;
#pragma unroll
        for (int j = 0; j < 4; j++) {
            __half2 h0 = __floats2half2_rn(av[j].x, av[j].y);
            __half2 h1 = __floats2half2_rn(av[j].z, av[j].w);
            int e = (lrow * ASTR + lhalf + j * 4) * 2;
            *(__half2*)(asm_base + OFF_A + e) = h0;
            *(__half2*)(asm_base + OFF_A + e + 4) = h1;
        }
        if (ks < 7) {
#pragma unroll
            for (int j = 0; j < 4; j++)
                av[j] = rv ? *(const float4*)&x[(size_t)grow * 256 + (ks + 1) * 32 + lhalf + j * 4]
                           : make_float4(0.f, 0.f, 0.f, 0.f);
        }
        asm volatile("cp.async.wait_group 0;");
        __syncthreads();
        if (ks < 7) ISSUE_B(stage ^ 1, ks + 1);

        uint32_t a_sm = base + OFF_A, b_sm = base + OFF_B;
#pragma unroll
        for (int kk = 0; kk < 2; kk++) {
            int colk = kk * 16;
            uint32_t bf[4][2];
#pragma unroll
            for (int nt = 0; nt < 4; nt++) {
                uint32_t off = (uint32_t)(((b_r + nt * 8) * ASTR + colk + b_c8) * 2);
                ldm_x2(bf[nt][0], bf[nt][1], b_sm + off);
            }
#pragma unroll
            for (int mt = 0; mt < 4; mt++) {
                uint32_t off = (uint32_t)(((a_r + mt * 16) * ASTR + colk + a_c8) * 2);
                uint32_t a0, a1, a2, a3;
                ldm_x4(a0, a1, a2, a3, a_sm + off);
#pragma unroll
                for (int nt = 0; nt < 4; nt++)
                    mma16816f(acc[mt][nt], a0, a1, a2, a3, bf[nt][0], bf[nt][1]);
            }
        }
    }
#undef ISSUE_B

    // --- epilogue: store h1 (fp32) + fused a_s1/a_d1 ---
    int head = (col0 >> 5) + warp_n;
    int colw = col0 + warp_n * 32;
    int quad = lane >> 2, qt = lane & 3;

    float aS[4][2], aD[4][2];
#pragma unroll
    for (int nt = 0; nt < 4; nt++) {
        int c = colw + nt * 8 + qt * 2;
        aS[nt][0] = __ldg(&attS[c]);     aS[nt][1] = __ldg(&attS[c + 1]);
        aD[nt][0] = __ldg(&attD[c]);     aD[nt][1] = __ldg(&attD[c + 1]);
    }
#pragma unroll
    for (int mt = 0; mt < 4; mt++) {
        int r_lo = row0 + warp_m * 64 + mt * 16 + quad;
        int r_hi = r_lo + 8;
        float s_lo = 0.f, d_lo = 0.f, s_hi = 0.f, d_hi = 0.f;
#pragma unroll
        for (int nt = 0; nt < 4; nt++) {
            float c0 = acc[mt][nt][0], c1 = acc[mt][nt][1];
            float c2 = acc[mt][nt][2], c3 = acc[mt][nt][3];
            s_lo = fmaf(c0, aS[nt][0], fmaf(c1, aS[nt][1], s_lo));
            d_lo = fmaf(c0, aD[nt][0], fmaf(c1, aD[nt][1], d_lo));
            s_hi = fmaf(c2, aS[nt][0], fmaf(c3, aS[nt][1], s_hi));
            d_hi = fmaf(c2, aD[nt][0], fmaf(c3, aD[nt][1], d_hi));
            int c = colw + nt * 8 + qt * 2;
            if (r_lo < M) *(float2*)&g_h1[(size_t)r_lo * 256 + c] = make_float2(c0, c1);
            if (r_hi < M) *(float2*)&g_h1[(size_t)r_hi * 256 + c] = make_float2(c2, c3);
        }
#pragma unroll
        for (int off = 2; off > 0; off >>= 1) {
            s_lo += __shfl_xor_sync(0xffffffffu, s_lo, off);
            d_lo += __shfl_xor_sync(0xffffffffu, d_lo, off);
            s_hi += __shfl_xor_sync(0xffffffffu, s_hi, off);
            d_hi += __shfl_xor_sync(0xffffffffu, d_hi, off);
        }
        if (qt == 0) {
            if (r_lo < M) { g_as1[r_lo * 8 + head] = s_lo; g_ad1[r_lo * 8 + head] = d_lo; }
            if (r_hi < M) { g_as1[r_hi * 8 + head] = s_hi; g_ad1[r_hi * 8 + head] = d_hi; }
        }
    }
}

// ------------------------------ agg1 (warp per node, fp32 gathers) ---------
// lane owns features [lane*8, lane*8+8); head = lane>>2.  Single-pass softmax,
// per-lane denominator (replicated within quads).
__global__ void __launch_bounds__(128)
agg1_k(const float* __restrict__ b1, int N) {
    __shared__ float w_sh[4][32][9];
    __shared__ int   s_sh[4][32];
    int t = threadIdx.x, lane = t & 31, w = t >> 5;
    int n = blockIdx.x * 4 + w;
    if (n >= N) return;
    int deg = min(g_cnt[n], CAP);
    const int2* eb = &g_edge[n * CAP];
    int hq = lane >> 2;
    int fcol = lane * 8;

    float ad[8];
    {
        float4 d0 = __ldg((const float4*)&g_ad1[n * 8]);
        float4 d1 = __ldg((const float4*)&g_ad1[n * 8 + 4]);
        ad[0]=d0.x; ad[1]=d0.y; ad[2]=d0.z; ad[3]=d0.w;
        ad[4]=d1.x; ad[5]=d1.y; ad[6]=d1.z; ad[7]=d1.w;
    }

    float acc[8];
#pragma unroll
    for (int i = 0; i < 8; i++) acc[i] = 0.f;
    float dn = 0.f;

    for (int b0 = 0; b0 < deg; b0 += 32) {
        int cnt = min(32, deg - b0);
        if (lane < cnt) {
            int2 e = eb[b0 + lane];
            int s = e.x;
            float ww = __int_as_float(e.y);
            s_sh[w][lane] = s;
            float4 a0 = __ldg((const float4*)&g_as1[s * 8]);
            float4 a1 = __ldg((const float4*)&g_as1[s * 8 + 4]);
            float as[8] = {a0.x, a0.y, a0.z, a0.w, a1.x, a1.y, a1.z, a1.w};
#pragma unroll
            for (int h = 0; h < 8; h++) {
                float lg = as[h] + ad[h];
                lg = lg > 0.f ? lg : 0.2f * lg;
                w_sh[w][lane][h] = __expf(lg * ww);
            }
        }
        __syncwarp();
        int jj = 0;
        for (; jj + 2 <= cnt; jj += 2) {
            int s0 = s_sh[w][jj], s1 = s_sh[w][jj + 1];
            float w0 = w_sh[w][jj][hq], w1 = w_sh[w][jj + 1][hq];
            const float4* p0 = (const float4*)&g_h1[(size_t)s0 * 256 + fcol];
            const float4* p1 = (const float4*)&g_h1[(size_t)s1 * 256 + fcol];
            float4 u0 = p0[0], u1 = p0[1];
            float4 v0 = p1[0], v1 = p1[1];
            acc[0]=fmaf(w0,u0.x,acc[0]); acc[1]=fmaf(w0,u0.y,acc[1]);
            acc[2]=fmaf(w0,u0.z,acc[2]); acc[3]=fmaf(w0,u0.w,acc[3]);
            acc[4]=fmaf(w0,u1.x,acc[4]); acc[5]=fmaf(w0,u1.y,acc[5]);
            acc[6]=fmaf(w0,u1.z,acc[6]); acc[7]=fmaf(w0,u1.w,acc[7]);
            acc[0]=fmaf(w1,v0.x,acc[0]); acc[1]=fmaf(w1,v0.y,acc[1]);
            acc[2]=fmaf(w1,v0.z,acc[2]); acc[3]=fmaf(w1,v0.w,acc[3]);
            acc[4]=fmaf(w1,v1.x,acc[4]); acc[5]=fmaf(w1,v1.y,acc[5]);
            acc[6]=fmaf(w1,v1.z,acc[6]); acc[7]=fmaf(w1,v1.w,acc[7]);
            dn += w0 + w1;
        }
        for (; jj < cnt; jj++) {
            int s0 = s_sh[w][jj];
            float w0 = w_sh[w][jj][hq];
            const float4* p0 = (const float4*)&g_h1[(size_t)s0 * 256 + fcol];
            float4 u0 = p0[0], u1 = p0[1];
            acc[0]=fmaf(w0,u0.x,acc[0]); acc[1]=fmaf(w0,u0.y,acc[1]);
            acc[2]=fmaf(w0,u0.z,acc[2]); acc[3]=fmaf(w0,u0.w,acc[3]);
            acc[4]=fmaf(w0,u1.x,acc[4]); acc[5]=fmaf(w0,u1.y,acc[5]);
            acc[6]=fmaf(w0,u1.z,acc[6]); acc[7]=fmaf(w0,u1.w,acc[7]);
            dn += w0;
        }
        __syncwarp();
    }

    float inv = 1.f / (dn + 1e-16f);
    float4 bA = __ldg((const float4*)&b1[fcol]);
    float4 bB = __ldg((const float4*)&b1[fcol + 4]);
    float bb[8] = {bA.x, bA.y, bA.z, bA.w, bB.x, bB.y, bB.z, bB.w};
    __half2 outp[4];
#pragma unroll
    for (int i = 0; i < 4; i++) {
        float o0 = acc[2*i]     * inv + bb[2*i];
        float o1 = acc[2*i + 1] * inv + bb[2*i + 1];
        o0 = o0 > 0.f ? o0 : (__expf(o0) - 1.f);   // ELU
        o1 = o1 > 0.f ? o1 : (__expf(o1) - 1.f);
        outp[i] = __floats2half2_rn(o0, o1);
    }
    *(uint4*)&g_hEh[(size_t)n * 256 + fcol] = *(uint4*)outp;
}

// ------------------------------ GEMM2 + att2 (hE fp16) ---------------------
__global__ void gemm2_k(const float* __restrict__ W2, const float* __restrict__ attS,
                        const float* __restrict__ attD, int N) {
    __shared__ float Ws[256 * 17];
    int t = threadIdx.x;
    for (int idx = t; idx < 4096; idx += 256)
        Ws[(idx >> 4) * 17 + (idx & 15)] = W2[idx];
    __syncthreads();
    int lane = t & 31;
    int n = blockIdx.x * 8 + (t >> 5);
    if (n >= N) return;
    const __half* row = g_hEh + (size_t)n * 256;
    float acc[16];
#pragma unroll
    for (int c = 0; c < 16; c++) acc[c] = 0.f;
#pragma unroll
    for (int kb = 0; kb < 8; kb++) {
        int k = kb * 32 + lane;
        float v = __half2float(row[k]);
        const float* wp = &Ws[k * 17];
#pragma unroll
        for (int c = 0; c < 16; c++) acc[c] = fmaf(v, wp[c], acc[c]);
    }
#pragma unroll
    for (int off = 16; off > 0; off >>= 1)
#pragma unroll
        for (int c = 0; c < 16; c++)
            acc[c] += __shfl_xor_sync(0xffffffffu, acc[c], off);
    if (lane == 0) {
        float as = 0.f, adv = 0.f;
#pragma unroll
        for (int c = 0; c < 16; c++) {
            g_h2[n * 16 + c] = acc[c];
            as  = fmaf(acc[c], attS[c], as);
            adv = fmaf(acc[c], attD[c], adv);
        }
        g_as2[n] = as;
        g_ad2[n] = adv;
    }
}

// ------------------------------ agg2 (16 lanes per node) -------------------
__global__ void agg2_k(const float* __restrict__ b2, float* __restrict__ out, int N) {
    int t = threadIdx.x;
    int lane16 = t & 15;
    int n = blockIdx.x * 16 + (t >> 4);
    if (n >= N) return;
    int deg = min(g_cnt[n], CAP);
    const int2* eb = &g_edge[n * CAP];
    float adv = g_ad2[n];
    float acc[16];
#pragma unroll
    for (int c = 0; c < 16; c++) acc[c] = 0.f;
    float dn = 0.f;
    for (int j = lane16; j < deg; j += 16) {
        int2 e = eb[j];
        int s = e.x;
        float eww = __int_as_float(e.y);
        float lg = g_as2[s] + adv;
        lg = lg > 0.f ? lg : 0.2f * lg;
        float wv = __expf(lg * eww);
        dn += wv;
        const float4* hp = (const float4*)&g_h2[s * 16];
        float4 v0 = hp[0], v1 = hp[1], v2 = hp[2], v3 = hp[3];
        acc[0]  = fmaf(wv, v0.x, acc[0]);  acc[1]  = fmaf(wv, v0.y, acc[1]);
        acc[2]  = fmaf(wv, v0.z, acc[2]);  acc[3]  = fmaf(wv, v0.w, acc[3]);
        acc[4]  = fmaf(wv, v1.x, acc[4]);  acc[5]  = fmaf(wv, v1.y, acc[5]);
        acc[6]  = fmaf(wv, v1.z, acc[6]);  acc[7]  = fmaf(wv, v1.w, acc[7]);
        acc[8]  = fmaf(wv, v2.x, acc[8]);  acc[9]  = fmaf(wv, v2.y, acc[9]);
        acc[10] = fmaf(wv, v2.z, acc[10]); acc[11] = fmaf(wv, v2.w, acc[11]);
        acc[12] = fmaf(wv, v3.x, acc[12]); acc[13] = fmaf(wv, v3.y, acc[13]);
        acc[14] = fmaf(wv, v3.z, acc[14]); acc[15] = fmaf(wv, v3.w, acc[15]);
    }
#pragma unroll
    for (int off = 8; off > 0; off >>= 1) {
        dn += __shfl_xor_sync(0xffffffffu, dn, off);
#pragma unroll
        for (int c = 0; c < 16; c++)
            acc[c] += __shfl_xor_sync(0xffffffffu, acc[c], off);
    }
    if (lane16 == 0) {
        float inv = 1.f / (dn + 1e-16f);
#pragma unroll
        for (int c = 0; c < 16; c++)
            out[(size_t)n * 16 + c] = fmaf(acc[c], inv, b2[c]);
    }
}

// ---------------------------------------------------------------------------
extern "C" void kernel_launch(void* const* d_in, const int* in_sizes, int n_in,
                              void* d_out, int out_size) {
    const float* x     = (const float*)d_in[0];
    const int*   ei    = (const int*)  d_in[1];
    const float* ew    = (const float*)d_in[2];
    const float* W1    = (const float*)d_in[3];
    const float* attS1 = (const float*)d_in[4];
    const float* attD1 = (const float*)d_in[5];
    const float* b1    = (const float*)d_in[6];
    const float* W2    = (const float*)d_in[7];
    const float* attS2 = (const float*)d_in[8];
    const float* attD2 = (const float*)d_in[9];
    const float* b2    = (const float*)d_in[10];
    float* out = (float*)d_out;

    int N  = in_sizes[0] / 256;
    int E  = in_sizes[2];
    int ET = E + N;

    cudaFuncSetAttribute(gemm1_mma, cudaFuncAttributeMaxDynamicSharedMemorySize,
                         G1_SMEM);

    // prep (zero counters + W1 fp16 transpose), then bucketed edge sort
    prep_k<<<(65536 + 255) / 256, 256>>>(W1, N);
    scatter_k<<<(ET / 4 + 256) / 256, 256>>>(ei, ew, E, ET);

    // layer 1
    gemm1_mma<<<dim3((N + 127) / 128, 2), 256, G1_SMEM>>>(x, attS1, attD1, N);
    agg1_k<<<(N + 3) / 4, 128>>>(b1, N);

    // layer 2
    gemm2_k<<<(N + 7) / 8, 256>>>(W2, attS2, attD2, N);
    agg2_k<<<(N + 15) / 16, 256>>>(b2, out, N);
}

// round 14
// speedup vs baseline: 1.1143x; 1.1143x over previous
#include <cuda_runtime.h>
#include <cuda_bf16.h>
#include <cuda_fp16.h>
#include <cstdint>

// ---------------------------------------------------------------------------
// GAT 2-layer forward, round 14 (round-10 config, 5 launches):
//   - scatter: bucketed counting sort by dst (int4-vectorized) + W1 fp16
//     transpose folded in (first 65536 threads)
//   - GEMM1: fp16 mma.sync m16n8k16 (fp32 accum), 1-sync pipeline; att1 fused;
//     h1 -> fp16  (L1-wavefront-bound gather prefers half rows)
//   - agg1: warp per node (8 warps/block); lane owns 8 features; single-pass
//     softmax; ELU; hE -> fp16
//   - gemm2: warp per node (hE fp16 @ W2) + fused a_s2/a_d2
//   - agg2: 16 lanes per node -> out; re-zeroes g_cnt for the next replay
//     (device globals start zeroed; every launch restores the invariant)
// ---------------------------------------------------------------------------

#define NMAX 20000
#define EMAX 320000
#define CAP  128

__device__ int   g_cnt[NMAX];                 // ZERO at entry (module init /
                                              // re-zeroed by agg2 each launch)
__device__ int2  g_edge[NMAX * CAP];
__device__ __half g_Bf[256 * 256];            // W1^T fp16, [N=256][K=256]
__device__ __half g_h1h[(size_t)NMAX * 256];  // h1 fp16
__device__ __half g_hEh[(size_t)NMAX * 256];  // hE fp16
__device__ float g_as1[NMAX * 8];
__device__ float g_ad1[NMAX * 8];
__device__ float g_h2[NMAX * 16];
__device__ float g_as2[NMAX];
__device__ float g_ad2[NMAX];

// ------------------------------ helpers ------------------------------------
__device__ __forceinline__ uint32_t smem_u32(const void* p) {
    uint32_t a;
    asm("{ .reg .u64 t; cvta.to.shared.u64 t, %1; cvt.u32.u64 %0, t; }"
        : "=r"(a) : "l"(p));
    return a;
}
__device__ __forceinline__ void ldm_x4(uint32_t& r0, uint32_t& r1,
                                       uint32_t& r2, uint32_t& r3, uint32_t a) {
    asm volatile("ldmatrix.sync.aligned.m8n8.x4.shared.b16 {%0,%1,%2,%3}, [%4];"
                 : "=r"(r0), "=r"(r1), "=r"(r2), "=r"(r3) : "r"(a));
}
__device__ __forceinline__ void ldm_x2(uint32_t& r0, uint32_t& r1, uint32_t a) {
    asm volatile("ldmatrix.sync.aligned.m8n8.x2.shared.b16 {%0,%1}, [%2];"
                 : "=r"(r0), "=r"(r1) : "r"(a));
}
__device__ __forceinline__ void mma16816f(float* c, uint32_t a0, uint32_t a1,
                                          uint32_t a2, uint32_t a3,
                                          uint32_t b0, uint32_t b1) {
    asm volatile(
        "mma.sync.aligned.m16n8k16.row.col.f32.f16.f16.f32 "
        "{%0,%1,%2,%3},{%4,%5,%6,%7},{%8,%9},{%0,%1,%2,%3};"
        : "+f"(c[0]), "+f"(c[1]), "+f"(c[2]), "+f"(c[3])
        : "r"(a0), "r"(a1), "r"(a2), "r"(a3), "r"(b0), "r"(b1));
}
#define CP16(dst, src) \
    asm volatile("cp.async.cg.shared.global [%0], [%1], 16;" :: "r"(dst), "l"(src))
#define CP_COMMIT() asm volatile("cp.async.commit_group;")

// --------------- scatter (buckets) + W1 fp16 transpose fold-in -------------
__global__ void scatter_k(const int* __restrict__ ei, const float* __restrict__ ew,
                          const float* __restrict__ W1, int E, int ET) {
    int idx = blockIdx.x * blockDim.x + threadIdx.x;
    // fold in W1 -> fp16 transpose (idempotent; completes before gemm1 runs)
    if (idx < 65536) {
        int k = idx >> 8, n = idx & 255;      // W1 is [K=256][N=256]
        g_Bf[n * 256 + k] = __float2half_rn(W1[idx]);
    }
    int i0 = idx * 4;
    if (i0 >= ET) return;
    if (i0 + 3 < E) {
        int4   s4 = ((const int4*)ei)[idx];
        int4   d4 = ((const int4*)(ei + E))[idx];
        float4 w4 = ((const float4*)ew)[idx];
        int r;
        r = atomicAdd(&g_cnt[d4.x], 1);
        if (r < CAP) g_edge[d4.x * CAP + r] = make_int2(s4.x, __float_as_int(w4.x));
        r = atomicAdd(&g_cnt[d4.y], 1);
        if (r < CAP) g_edge[d4.y * CAP + r] = make_int2(s4.y, __float_as_int(w4.y));
        r = atomicAdd(&g_cnt[d4.z], 1);
        if (r < CAP) g_edge[d4.z * CAP + r] = make_int2(s4.z, __float_as_int(w4.z));
        r = atomicAdd(&g_cnt[d4.w], 1);
        if (r < CAP) g_edge[d4.w * CAP + r] = make_int2(s4.w, __float_as_int(w4.w));
    } else {
#pragma unroll
        for (int u = 0; u < 4; u++) {
            int i = i0 + u;
            if (i >= ET) break;
            int src, dst; float w;
            if (i < E) { src = ei[i]; dst = ei[E + i]; w = ew[i]; }
            else       { src = i - E; dst = i - E;     w = 1.0f; }
            int r = atomicAdd(&g_cnt[dst], 1);
            if (r < CAP) g_edge[dst * CAP + r] = make_int2(src, __float_as_int(w));
        }
    }
}

// ------------------------------ GEMM1 (fp16 HMMA, 1-sync pipeline) ---------
#define ASTR 40
#define TILEB 10240
#define STG  (2 * TILEB)
#define OFF_A 0
#define OFF_B TILEB
#define G1_SMEM (2 * STG)     // 40960

__global__ void __launch_bounds__(256, 2)
gemm1_mma(const float* __restrict__ x, const float* __restrict__ attS,
          const float* __restrict__ attD, int M) {
    extern __shared__ char dsm[];
    uint32_t sb = smem_u32(dsm);

    int tid = threadIdx.x, lane = tid & 31, wid = tid >> 5;
    int warp_m = wid & 1, warp_n = wid >> 1;
    int row0 = blockIdx.x * 128;
    int col0 = blockIdx.y * 128;

    float acc[4][4][4];
#pragma unroll
    for (int a = 0; a < 4; a++)
#pragma unroll
        for (int b = 0; b < 4; b++)
#pragma unroll
            for (int c = 0; c < 4; c++) acc[a][b][c] = 0.f;

    int lrow = tid >> 1, lhalf = (tid & 1) * 16;
    int grow = row0 + lrow;
    bool rv = grow < M;
    const char* b_src = (const char*)&g_Bf[(col0 + lrow) * 256 + lhalf];
    uint32_t doff = (uint32_t)((lrow * ASTR + lhalf) * 2);

    int a_r = warp_m * 64 + (lane & 15);
    int a_c8 = (lane >> 4) * 8;
    int b_r = warp_n * 32 + (lane & 7);
    int b_c8 = ((lane >> 3) & 1) * 8;

#define ISSUE_B(stage, ks) do {                                            \
        uint32_t _b = sb + (uint32_t)(stage) * STG;                        \
        int _kb = (ks) * 64;                                               \
        CP16(_b + OFF_B + doff,      b_src + _kb);                         \
        CP16(_b + OFF_B + doff + 16, b_src + _kb + 16);                    \
        CP_COMMIT();                                                       \
    } while (0)

    float4 av[4];
#pragma unroll
    for (int j = 0; j < 4; j++)
        av[j] = rv ? *(const float4*)&x[(size_t)grow * 256 + lhalf + j * 4]
                   : make_float4(0.f, 0.f, 0.f, 0.f);
    ISSUE_B(0, 0);

    for (int ks = 0; ks < 8; ks++) {
        int stage = ks & 1;
        uint32_t base = sb + (uint32_t)stage * STG;

        char* asm_base = dsm + (size_t)stage * STG;
#pragma unroll
        for (int j = 0; j < 4; j++) {
            __half2 h0 = __floats2half2_rn(av[j].x, av[j].y);
            __half2 h1 = __floats2half2_rn(av[j].z, av[j].w);
            int e = (lrow * ASTR + lhalf + j * 4) * 2;
            *(__half2*)(asm_base + OFF_A + e) = h0;
            *(__half2*)(asm_base + OFF_A + e + 4) = h1;
        }
        if (ks < 7) {
#pragma unroll
            for (int j = 0; j < 4; j++)
                av[j] = rv ? *(const float4*)&x[(size_t)grow * 256 + (ks + 1) * 32 + lhalf + j * 4]
                           : make_float4(0.f, 0.f, 0.f, 0.f);
        }
        asm volatile("cp.async.wait_group 0;");
        __syncthreads();
        if (ks < 7) ISSUE_B(stage ^ 1, ks + 1);

        uint32_t a_sm = base + OFF_A, b_sm = base + OFF_B;
#pragma unroll
        for (int kk = 0; kk < 2; kk++) {
            int colk = kk * 16;
            uint32_t bf[4][2];
#pragma unroll
            for (int nt = 0; nt < 4; nt++) {
                uint32_t off = (uint32_t)(((b_r + nt * 8) * ASTR + colk + b_c8) * 2);
                ldm_x2(bf[nt][0], bf[nt][1], b_sm + off);
            }
#pragma unroll
            for (int mt = 0; mt < 4; mt++) {
                uint32_t off = (uint32_t)(((a_r + mt * 16) * ASTR + colk + a_c8) * 2);
                uint32_t a0, a1, a2, a3;
                ldm_x4(a0, a1, a2, a3, a_sm + off);
#pragma unroll
                for (int nt = 0; nt < 4; nt++)
                    mma16816f(acc[mt][nt], a0, a1, a2, a3, bf[nt][0], bf[nt][1]);
            }
        }
    }
#undef ISSUE_B

    // --- epilogue: store h1 (fp16) + fused a_s1/a_d1 ---
    int head = (col0 >> 5) + warp_n;
    int colw = col0 + warp_n * 32;
    int quad = lane >> 2, qt = lane & 3;

    float aS[4][2], aD[4][2];
#pragma unroll
    for (int nt = 0; nt < 4; nt++) {
        int c = colw + nt * 8 + qt * 2;
        aS[nt][0] = __ldg(&attS[c]);     aS[nt][1] = __ldg(&attS[c + 1]);
        aD[nt][0] = __ldg(&attD[c]);     aD[nt][1] = __ldg(&attD[c + 1]);
    }
#pragma unroll
    for (int mt = 0; mt < 4; mt++) {
        int r_lo = row0 + warp_m * 64 + mt * 16 + quad;
        int r_hi = r_lo + 8;
        float s_lo = 0.f, d_lo = 0.f, s_hi = 0.f, d_hi = 0.f;
#pragma unroll
        for (int nt = 0; nt < 4; nt++) {
            float c0 = acc[mt][nt][0], c1 = acc[mt][nt][1];
            float c2 = acc[mt][nt][2], c3 = acc[mt][nt][3];
            s_lo = fmaf(c0, aS[nt][0], fmaf(c1, aS[nt][1], s_lo));
            d_lo = fmaf(c0, aD[nt][0], fmaf(c1, aD[nt][1], d_lo));
            s_hi = fmaf(c2, aS[nt][0], fmaf(c3, aS[nt][1], s_hi));
            d_hi = fmaf(c2, aD[nt][0], fmaf(c3, aD[nt][1], d_hi));
            int c = colw + nt * 8 + qt * 2;
            if (r_lo < M) *(__half2*)&g_h1h[(size_t)r_lo * 256 + c] = __floats2half2_rn(c0, c1);
            if (r_hi < M) *(__half2*)&g_h1h[(size_t)r_hi * 256 + c] = __floats2half2_rn(c2, c3);
        }
#pragma unroll
        for (int off = 2; off > 0; off >>= 1) {
            s_lo += __shfl_xor_sync(0xffffffffu, s_lo, off);
            d_lo += __shfl_xor_sync(0xffffffffu, d_lo, off);
            s_hi += __shfl_xor_sync(0xffffffffu, s_hi, off);
            d_hi += __shfl_xor_sync(0xffffffffu, d_hi, off);
        }
        if (qt == 0) {
            if (r_lo < M) { g_as1[r_lo * 8 + head] = s_lo; g_ad1[r_lo * 8 + head] = d_lo; }
            if (r_hi < M) { g_as1[r_hi * 8 + head] = s_hi; g_ad1[r_hi * 8 + head] = d_hi; }
        }
    }
}

// ------------------------------ agg1 (warp per node, 8 warps/block) --------
// lane owns features [lane*8, lane*8+8); head = lane>>2.  Single-pass softmax,
// per-lane denominator (replicated within quads, no reduction needed).
__global__ void __launch_bounds__(256)
agg1_k(const float* __restrict__ b1, int N) {
    __shared__ float w_sh[8][32][9];
    __shared__ int   s_sh[8][32];
    int t = threadIdx.x, lane = t & 31, w = t >> 5;
    int n = blockIdx.x * 8 + w;
    if (n >= N) return;
    int deg = min(g_cnt[n], CAP);
    const int2* eb = &g_edge[n * CAP];
    int hq = lane >> 2;
    int fcol = lane * 8;

    float ad[8];
    {
        float4 d0 = __ldg((const float4*)&g_ad1[n * 8]);
        float4 d1 = __ldg((const float4*)&g_ad1[n * 8 + 4]);
        ad[0]=d0.x; ad[1]=d0.y; ad[2]=d0.z; ad[3]=d0.w;
        ad[4]=d1.x; ad[5]=d1.y; ad[6]=d1.z; ad[7]=d1.w;
    }

    float acc[8];
#pragma unroll
    for (int i = 0; i < 8; i++) acc[i] = 0.f;
    float dn = 0.f;

    for (int b0 = 0; b0 < deg; b0 += 32) {
        int cnt = min(32, deg - b0);
        if (lane < cnt) {
            int2 e = eb[b0 + lane];
            int s = e.x;
            float ww = __int_as_float(e.y);
            s_sh[w][lane] = s;
            float4 a0 = __ldg((const float4*)&g_as1[s * 8]);
            float4 a1 = __ldg((const float4*)&g_as1[s * 8 + 4]);
            float as[8] = {a0.x, a0.y, a0.z, a0.w, a1.x, a1.y, a1.z, a1.w};
#pragma unroll
            for (int h = 0; h < 8; h++) {
                float lg = as[h] + ad[h];
                lg = lg > 0.f ? lg : 0.2f * lg;
                w_sh[w][lane][h] = __expf(lg * ww);
            }
        }
        __syncwarp();
        int jj = 0;
        for (; jj + 2 <= cnt; jj += 2) {
            int s0 = s_sh[w][jj], s1 = s_sh[w][jj + 1];
            float w0 = w_sh[w][jj][hq], w1 = w_sh[w][jj + 1][hq];
            uint4 v0 = *(const uint4*)&g_h1h[(size_t)s0 * 256 + fcol];
            uint4 v1 = *(const uint4*)&g_h1h[(size_t)s1 * 256 + fcol];
            float2 f;
            f = __half22float2(*(__half2*)&v0.x); acc[0]=fmaf(w0,f.x,acc[0]); acc[1]=fmaf(w0,f.y,acc[1]);
            f = __half22float2(*(__half2*)&v0.y); acc[2]=fmaf(w0,f.x,acc[2]); acc[3]=fmaf(w0,f.y,acc[3]);
            f = __half22float2(*(__half2*)&v0.z); acc[4]=fmaf(w0,f.x,acc[4]); acc[5]=fmaf(w0,f.y,acc[5]);
            f = __half22float2(*(__half2*)&v0.w); acc[6]=fmaf(w0,f.x,acc[6]); acc[7]=fmaf(w0,f.y,acc[7]);
            f = __half22float2(*(__half2*)&v1.x); acc[0]=fmaf(w1,f.x,acc[0]); acc[1]=fmaf(w1,f.y,acc[1]);
            f = __half22float2(*(__half2*)&v1.y); acc[2]=fmaf(w1,f.x,acc[2]); acc[3]=fmaf(w1,f.y,acc[3]);
            f = __half22float2(*(__half2*)&v1.z); acc[4]=fmaf(w1,f.x,acc[4]); acc[5]=fmaf(w1,f.y,acc[5]);
            f = __half22float2(*(__half2*)&v1.w); acc[6]=fmaf(w1,f.x,acc[6]); acc[7]=fmaf(w1,f.y,acc[7]);
            dn += w0 + w1;
        }
        for (; jj < cnt; jj++) {
            int s0 = s_sh[w][jj];
            float w0 = w_sh[w][jj][hq];
            uint4 v0 = *(const uint4*)&g_h1h[(size_t)s0 * 256 + fcol];
            float2 f;
            f = __half22float2(*(__half2*)&v0.x); acc[0]=fmaf(w0,f.x,acc[0]); acc[1]=fmaf(w0,f.y,acc[1]);
            f = __half22float2(*(__half2*)&v0.y); acc[2]=fmaf(w0,f.x,acc[2]); acc[3]=fmaf(w0,f.y,acc[3]);
            f = __half22float2(*(__half2*)&v0.z); acc[4]=fmaf(w0,f.x,acc[4]); acc[5]=fmaf(w0,f.y,acc[5]);
            f = __half22float2(*(__half2*)&v0.w); acc[6]=fmaf(w0,f.x,acc[6]); acc[7]=fmaf(w0,f.y,acc[7]);
            dn += w0;
        }
        __syncwarp();
    }

    float inv = 1.f / (dn + 1e-16f);
    float4 bA = __ldg((const float4*)&b1[fcol]);
    float4 bB = __ldg((const float4*)&b1[fcol + 4]);
    float bb[8] = {bA.x, bA.y, bA.z, bA.w, bB.x, bB.y, bB.z, bB.w};
    __half2 outp[4];
#pragma unroll
    for (int i = 0; i < 4; i++) {
        float o0 = acc[2*i]     * inv + bb[2*i];
        float o1 = acc[2*i + 1] * inv + bb[2*i + 1];
        o0 = o0 > 0.f ? o0 : (__expf(o0) - 1.f);   // ELU
        o1 = o1 > 0.f ? o1 : (__expf(o1) - 1.f);
        outp[i] = __floats2half2_rn(o0, o1);
    }
    *(uint4*)&g_hEh[(size_t)n * 256 + fcol] = *(uint4*)outp;
}

// ------------------------------ GEMM2 + att2 (hE fp16) ---------------------
__global__ void gemm2_k(const float* __restrict__ W2, const float* __restrict__ attS,
                        const float* __restrict__ attD, int N) {
    __shared__ float Ws[256 * 17];
    int t = threadIdx.x;
    for (int idx = t; idx < 4096; idx += 256)
        Ws[(idx >> 4) * 17 + (idx & 15)] = W2[idx];
    __syncthreads();
    int lane = t & 31;
    int n = blockIdx.x * 8 + (t >> 5);
    if (n >= N) return;
    const __half* row = g_hEh + (size_t)n * 256;
    float acc[16];
#pragma unroll
    for (int c = 0; c < 16; c++) acc[c] = 0.f;
#pragma unroll
    for (int kb = 0; kb < 8; kb++) {
        int k = kb * 32 + lane;
        float v = __half2float(row[k]);
        const float* wp = &Ws[k * 17];
#pragma unroll
        for (int c = 0; c < 16; c++) acc[c] = fmaf(v, wp[c], acc[c]);
    }
#pragma unroll
    for (int off = 16; off > 0; off >>= 1)
#pragma unroll
        for (int c = 0; c < 16; c++)
            acc[c] += __shfl_xor_sync(0xffffffffu, acc[c], off);
    if (lane == 0) {
        float as = 0.f, adv = 0.f;
#pragma unroll
        for (int c = 0; c < 16; c++) {
            g_h2[n * 16 + c] = acc[c];
            as  = fmaf(acc[c], attS[c], as);
            adv = fmaf(acc[c], attD[c], adv);
        }
        g_as2[n] = as;
        g_ad2[n] = adv;
    }
}

// --------------- agg2 (16 lanes per node) + counter re-zero ----------------
__global__ void agg2_k(const float* __restrict__ b2, float* __restrict__ out, int N) {
    int t = threadIdx.x;
    int lane16 = t & 15;
    int n = blockIdx.x * 16 + (t >> 4);
    if (n >= N) return;
    int deg = min(g_cnt[n], CAP);
    const int2* eb = &g_edge[n * CAP];
    float adv = g_ad2[n];
    float acc[16];
#pragma unroll
    for (int c = 0; c < 16; c++) acc[c] = 0.f;
    float dn = 0.f;
    for (int j = lane16; j < deg; j += 16) {
        int2 e = eb[j];
        int s = e.x;
        float eww = __int_as_float(e.y);
        float lg = g_as2[s] + adv;
        lg = lg > 0.f ? lg : 0.2f * lg;
        float wv = __expf(lg * eww);
        dn += wv;
        const float4* hp = (const float4*)&g_h2[s * 16];
        float4 v0 = hp[0], v1 = hp[1], v2 = hp[2], v3 = hp[3];
        acc[0]  = fmaf(wv, v0.x, acc[0]);  acc[1]  = fmaf(wv, v0.y, acc[1]);
        acc[2]  = fmaf(wv, v0.z, acc[2]);  acc[3]  = fmaf(wv, v0.w, acc[3]);
        acc[4]  = fmaf(wv, v1.x, acc[4]);  acc[5]  = fmaf(wv, v1.y, acc[5]);
        acc[6]  = fmaf(wv, v1.z, acc[6]);  acc[7]  = fmaf(wv, v1.w, acc[7]);
        acc[8]  = fmaf(wv, v2.x, acc[8]);  acc[9]  = fmaf(wv, v2.y, acc[9]);
        acc[10] = fmaf(wv, v2.z, acc[10]); acc[11] = fmaf(wv, v2.w, acc[11]);
        acc[12] = fmaf(wv, v3.x, acc[12]); acc[13] = fmaf(wv, v3.y, acc[13]);
        acc[14] = fmaf(wv, v3.z, acc[14]); acc[15] = fmaf(wv, v3.w, acc[15]);
    }
#pragma unroll
    for (int off = 8; off > 0; off >>= 1) {
        dn += __shfl_xor_sync(0xffffffffu, dn, off);
#pragma unroll
        for (int c = 0; c < 16; c++)
            acc[c] += __shfl_xor_sync(0xffffffffu, acc[c], off);
    }
    if (lane16 == 0) {
        float inv = 1.f / (dn + 1e-16f);
#pragma unroll
        for (int c = 0; c < 16; c++)
            out[(size_t)n * 16 + c] = fmaf(acc[c], inv, b2[c]);
        g_cnt[n] = 0;          // restore invariant for the next graph replay
    }
}

// ---------------------------------------------------------------------------
extern "C" void kernel_launch(void* const* d_in, const int* in_sizes, int n_in,
                              void* d_out, int out_size) {
    const float* x     = (const float*)d_in[0];
    const int*   ei    = (const int*)  d_in[1];
    const float* ew    = (const float*)d_in[2];
    const float* W1    = (const float*)d_in[3];
    const float* attS1 = (const float*)d_in[4];
    const float* attD1 = (const float*)d_in[5];
    const float* b1    = (const float*)d_in[6];
    const float* W2    = (const float*)d_in[7];
    const float* attS2 = (const float*)d_in[8];
    const float* attD2 = (const float*)d_in[9];
    const float* b2    = (const float*)d_in[10];
    float* out = (float*)d_out;

    int N  = in_sizes[0] / 256;
    int E  = in_sizes[2];
    int ET = E + N;

    cudaFuncSetAttribute(gemm1_mma, cudaFuncAttributeMaxDynamicSharedMemorySize,
                         G1_SMEM);

    // bucketed edge sort (g_cnt is zero at entry) + W1 fp16 fold-in
    int sc_threads = max((ET + 3) / 4, 65536);
    scatter_k<<<(sc_threads + 255) / 256, 256>>>(ei, ew, W1, E, ET);

    // layer 1
    gemm1_mma<<<dim3((N + 127) / 128, 2), 256, G1_SMEM>>>(x, attS1, attD1, N);
    agg1_k<<<(N + 7) / 8, 256>>>(b1, N);

    // layer 2
    gemm2_k<<<(N + 7) / 8, 256>>>(W2, attS2, attD2, N);
    agg2_k<<<(N + 15) / 16, 256>>>(b2, out, N);
}

// round 15
// speedup vs baseline: 1.3868x; 1.2445x over previous
#include <cuda_runtime.h>
#include <cuda_bf16.h>
#include <cuda_fp16.h>
#include <cstdint>

// ---------------------------------------------------------------------------
// GAT 2-layer forward, round 15 (gemm2 -> HMMA):
//   - scatter: bucketed counting sort by dst + W1/W2 fp16 transposes folded in
//   - GEMM1: fp16 mma.sync m16n8k16 (fp32 accum), 1-sync pipeline; att1 fused;
//     h1 -> fp16
//   - agg1: warp per node (8 warps/block); single-pass softmax; ELU; hE->fp16
//   - GEMM2: fp16 HMMA, 128 nodes/block, full W2 in smem, hE streamed via
//     cp.async double-buffer; h2 + a_s2/a_d2 fused in epilogue
//   - agg2: 16 lanes per node -> out; re-zeroes g_cnt for next replay
// ---------------------------------------------------------------------------

#define NMAX 20000
#define NPAD 20096
#define EMAX 320000
#define CAP  128

__device__ int   g_cnt[NMAX];                 // zero at entry; agg2 re-zeroes
__device__ int2  g_edge[NMAX * CAP];
__device__ __half g_Bf[256 * 256];            // W1^T fp16, [N=256][K=256]
__device__ __half g_B2f[16 * 256];            // W2^T fp16, [N=16][K=256]
__device__ __half g_h1h[(size_t)NMAX * 256];  // h1 fp16
__device__ __half g_hEh[(size_t)NPAD * 256];  // hE fp16 (padded rows stay 0)
__device__ float g_as1[NMAX * 8];
__device__ float g_ad1[NMAX * 8];
__device__ float g_h2[NMAX * 16];
__device__ float g_as2[NMAX];
__device__ float g_ad2[NMAX];

// ------------------------------ helpers ------------------------------------
__device__ __forceinline__ uint32_t smem_u32(const void* p) {
    uint32_t a;
    asm("{ .reg .u64 t; cvta.to.shared.u64 t, %1; cvt.u32.u64 %0, t; }"
        : "=r"(a) : "l"(p));
    return a;
}
__device__ __forceinline__ void ldm_x4(uint32_t& r0, uint32_t& r1,
                                       uint32_t& r2, uint32_t& r3, uint32_t a) {
    asm volatile("ldmatrix.sync.aligned.m8n8.x4.shared.b16 {%0,%1,%2,%3}, [%4];"
                 : "=r"(r0), "=r"(r1), "=r"(r2), "=r"(r3) : "r"(a));
}
__device__ __forceinline__ void ldm_x2(uint32_t& r0, uint32_t& r1, uint32_t a) {
    asm volatile("ldmatrix.sync.aligned.m8n8.x2.shared.b16 {%0,%1}, [%2];"
                 : "=r"(r0), "=r"(r1) : "r"(a));
}
__device__ __forceinline__ void mma16816f(float* c, uint32_t a0, uint32_t a1,
                                          uint32_t a2, uint32_t a3,
                                          uint32_t b0, uint32_t b1) {
    asm volatile(
        "mma.sync.aligned.m16n8k16.row.col.f32.f16.f16.f32 "
        "{%0,%1,%2,%3},{%4,%5,%6,%7},{%8,%9},{%0,%1,%2,%3};"
        : "+f"(c[0]), "+f"(c[1]), "+f"(c[2]), "+f"(c[3])
        : "r"(a0), "r"(a1), "r"(a2), "r"(a3), "r"(b0), "r"(b1));
}
#define CP16(dst, src) \
    asm volatile("cp.async.cg.shared.global [%0], [%1], 16;" :: "r"(dst), "l"(src))
#define CP_COMMIT() asm volatile("cp.async.commit_group;")

// --------------- scatter (buckets) + W1/W2 fp16 fold-in --------------------
__global__ void scatter_k(const int* __restrict__ ei, const float* __restrict__ ew,
                          const float* __restrict__ W1, const float* __restrict__ W2,
                          int E, int ET) {
    int idx = blockIdx.x * blockDim.x + threadIdx.x;
    if (idx < 65536) {
        int k = idx >> 8, n = idx & 255;      // W1 is [K=256][N=256]
        g_Bf[n * 256 + k] = __float2half_rn(W1[idx]);
    }
    if (idx < 4096) {
        int k = idx >> 4, n = idx & 15;       // W2 is [K=256][N=16]
        g_B2f[n * 256 + k] = __float2half_rn(W2[idx]);
    }
    int i0 = idx * 4;
    if (i0 >= ET) return;
    if (i0 + 3 < E) {
        int4   s4 = ((const int4*)ei)[idx];
        int4   d4 = ((const int4*)(ei + E))[idx];
        float4 w4 = ((const float4*)ew)[idx];
        int r;
        r = atomicAdd(&g_cnt[d4.x], 1);
        if (r < CAP) g_edge[d4.x * CAP + r] = make_int2(s4.x, __float_as_int(w4.x));
        r = atomicAdd(&g_cnt[d4.y], 1);
        if (r < CAP) g_edge[d4.y * CAP + r] = make_int2(s4.y, __float_as_int(w4.y));
        r = atomicAdd(&g_cnt[d4.z], 1);
        if (r < CAP) g_edge[d4.z * CAP + r] = make_int2(s4.z, __float_as_int(w4.z));
        r = atomicAdd(&g_cnt[d4.w], 1);
        if (r < CAP) g_edge[d4.w * CAP + r] = make_int2(s4.w, __float_as_int(w4.w));
    } else {
#pragma unroll
        for (int u = 0; u < 4; u++) {
            int i = i0 + u;
            if (i >= ET) break;
            int src, dst; float w;
            if (i < E) { src = ei[i]; dst = ei[E + i]; w = ew[i]; }
            else       { src = i - E; dst = i - E;     w = 1.0f; }
            int r = atomicAdd(&g_cnt[dst], 1);
            if (r < CAP) g_edge[dst * CAP + r] = make_int2(src, __float_as_int(w));
        }
    }
}

// ------------------------------ GEMM1 (fp16 HMMA, 1-sync pipeline) ---------
#define ASTR 40
#define TILEB 10240
#define STG  (2 * TILEB)
#define OFF_A 0
#define OFF_B TILEB
#define G1_SMEM (2 * STG)     // 40960

__global__ void __launch_bounds__(256, 2)
gemm1_mma(const float* __restrict__ x, const float* __restrict__ attS,
          const float* __restrict__ attD, int M) {
    extern __shared__ char dsm[];
    uint32_t sb = smem_u32(dsm);

    int tid = threadIdx.x, lane = tid & 31, wid = tid >> 5;
    int warp_m = wid & 1, warp_n = wid >> 1;
    int row0 = blockIdx.x * 128;
    int col0 = blockIdx.y * 128;

    float acc[4][4][4];
#pragma unroll
    for (int a = 0; a < 4; a++)
#pragma unroll
        for (int b = 0; b < 4; b++)
#pragma unroll
            for (int c = 0; c < 4; c++) acc[a][b][c] = 0.f;

    int lrow = tid >> 1, lhalf = (tid & 1) * 16;
    int grow = row0 + lrow;
    bool rv = grow < M;
    const char* b_src = (const char*)&g_Bf[(col0 + lrow) * 256 + lhalf];
    uint32_t doff = (uint32_t)((lrow * ASTR + lhalf) * 2);

    int a_r = warp_m * 64 + (lane & 15);
    int a_c8 = (lane >> 4) * 8;
    int b_r = warp_n * 32 + (lane & 7);
    int b_c8 = ((lane >> 3) & 1) * 8;

#define ISSUE_B(stage, ks) do {                                            \
        uint32_t _b = sb + (uint32_t)(stage) * STG;                        \
        int _kb = (ks) * 64;                                               \
        CP16(_b + OFF_B + doff,      b_src + _kb);                         \
        CP16(_b + OFF_B + doff + 16, b_src + _kb + 16);                    \
        CP_COMMIT();                                                       \
    } while (0)

    float4 av[4];
#pragma unroll
    for (int j = 0; j < 4; j++)
        av[j] = rv ? *(const float4*)&x[(size_t)grow * 256 + lhalf + j * 4]
                   : make_float4(0.f, 0.f, 0.f, 0.f);
    ISSUE_B(0, 0);

    for (int ks = 0; ks < 8; ks++) {
        int stage = ks & 1;
        uint32_t base = sb + (uint32_t)stage * STG;

        char* asm_base = dsm + (size_t)stage * STG;
#pragma unroll
        for (int j = 0; j < 4; j++) {
            __half2 h0 = __floats2half2_rn(av[j].x, av[j].y);
            __half2 h1 = __floats2half2_rn(av[j].z, av[j].w);
            int e = (lrow * ASTR + lhalf + j * 4) * 2;
            *(__half2*)(asm_base + OFF_A + e) = h0;
            *(__half2*)(asm_base + OFF_A + e + 4) = h1;
        }
        if (ks < 7) {
#pragma unroll
            for (int j = 0; j < 4; j++)
                av[j] = rv ? *(const float4*)&x[(size_t)grow * 256 + (ks + 1) * 32 + lhalf + j * 4]
                           : make_float4(0.f, 0.f, 0.f, 0.f);
        }
        asm volatile("cp.async.wait_group 0;");
        __syncthreads();
        if (ks < 7) ISSUE_B(stage ^ 1, ks + 1);

        uint32_t a_sm = base + OFF_A, b_sm = base + OFF_B;
#pragma unroll
        for (int kk = 0; kk < 2; kk++) {
            int colk = kk * 16;
            uint32_t bf[4][2];
#pragma unroll
            for (int nt = 0; nt < 4; nt++) {
                uint32_t off = (uint32_t)(((b_r + nt * 8) * ASTR + colk + b_c8) * 2);
                ldm_x2(bf[nt][0], bf[nt][1], b_sm + off);
            }
#pragma unroll
            for (int mt = 0; mt < 4; mt++) {
                uint32_t off = (uint32_t)(((a_r + mt * 16) * ASTR + colk + a_c8) * 2);
                uint32_t a0, a1, a2, a3;
                ldm_x4(a0, a1, a2, a3, a_sm + off);
#pragma unroll
                for (int nt = 0; nt < 4; nt++)
                    mma16816f(acc[mt][nt], a0, a1, a2, a3, bf[nt][0], bf[nt][1]);
            }
        }
    }
#undef ISSUE_B

    // --- epilogue: store h1 (fp16) + fused a_s1/a_d1 ---
    int head = (col0 >> 5) + warp_n;
    int colw = col0 + warp_n * 32;
    int quad = lane >> 2, qt = lane & 3;

    float aS[4][2], aD[4][2];
#pragma unroll
    for (int nt = 0; nt < 4; nt++) {
        int c = colw + nt * 8 + qt * 2;
        aS[nt][0] = __ldg(&attS[c]);     aS[nt][1] = __ldg(&attS[c + 1]);
        aD[nt][0] = __ldg(&attD[c]);     aD[nt][1] = __ldg(&attD[c + 1]);
    }
#pragma unroll
    for (int mt = 0; mt < 4; mt++) {
        int r_lo = row0 + warp_m * 64 + mt * 16 + quad;
        int r_hi = r_lo + 8;
        float s_lo = 0.f, d_lo = 0.f, s_hi = 0.f, d_hi = 0.f;
#pragma unroll
        for (int nt = 0; nt < 4; nt++) {
            float c0 = acc[mt][nt][0], c1 = acc[mt][nt][1];
            float c2 = acc[mt][nt][2], c3 = acc[mt][nt][3];
            s_lo = fmaf(c0, aS[nt][0], fmaf(c1, aS[nt][1], s_lo));
            d_lo = fmaf(c0, aD[nt][0], fmaf(c1, aD[nt][1], d_lo));
            s_hi = fmaf(c2, aS[nt][0], fmaf(c3, aS[nt][1], s_hi));
            d_hi = fmaf(c2, aD[nt][0], fmaf(c3, aD[nt][1], d_hi));
            int c = colw + nt * 8 + qt * 2;
            if (r_lo < M) *(__half2*)&g_h1h[(size_t)r_lo * 256 + c] = __floats2half2_rn(c0, c1);
            if (r_hi < M) *(__half2*)&g_h1h[(size_t)r_hi * 256 + c] = __floats2half2_rn(c2, c3);
        }
#pragma unroll
        for (int off = 2; off > 0; off >>= 1) {
            s_lo += __shfl_xor_sync(0xffffffffu, s_lo, off);
            d_lo += __shfl_xor_sync(0xffffffffu, d_lo, off);
            s_hi += __shfl_xor_sync(0xffffffffu, s_hi, off);
            d_hi += __shfl_xor_sync(0xffffffffu, d_hi, off);
        }
        if (qt == 0) {
            if (r_lo < M) { g_as1[r_lo * 8 + head] = s_lo; g_ad1[r_lo * 8 + head] = d_lo; }
            if (r_hi < M) { g_as1[r_hi * 8 + head] = s_hi; g_ad1[r_hi * 8 + head] = d_hi; }
        }
    }
}

// ------------------------------ agg1 (warp per node, 8 warps/block) --------
__global__ void __launch_bounds__(256)
agg1_k(const float* __restrict__ b1, int N) {
    __shared__ float w_sh[8][32][9];
    __shared__ int   s_sh[8][32];
    int t = threadIdx.x, lane = t & 31, w = t >> 5;
    int n = blockIdx.x * 8 + w;
    if (n >= N) return;
    int deg = min(g_cnt[n], CAP);
    const int2* eb = &g_edge[n * CAP];
    int hq = lane >> 2;
    int fcol = lane * 8;

    float ad[8];
    {
        float4 d0 = __ldg((const float4*)&g_ad1[n * 8]);
        float4 d1 = __ldg((const float4*)&g_ad1[n * 8 + 4]);
        ad[0]=d0.x; ad[1]=d0.y; ad[2]=d0.z; ad[3]=d0.w;
        ad[4]=d1.x; ad[5]=d1.y; ad[6]=d1.z; ad[7]=d1.w;
    }

    float acc[8];
#pragma unroll
    for (int i = 0; i < 8; i++) acc[i] = 0.f;
    float dn = 0.f;

    for (int b0 = 0; b0 < deg; b0 += 32) {
        int cnt = min(32, deg - b0);
        if (lane < cnt) {
            int2 e = eb[b0 + lane];
            int s = e.x;
            float ww = __int_as_float(e.y);
            s_sh[w][lane] = s;
            float4 a0 = __ldg((const float4*)&g_as1[s * 8]);
            float4 a1 = __ldg((const float4*)&g_as1[s * 8 + 4]);
            float as[8] = {a0.x, a0.y, a0.z, a0.w, a1.x, a1.y, a1.z, a1.w};
#pragma unroll
            for (int h = 0; h < 8; h++) {
                float lg = as[h] + ad[h];
                lg = lg > 0.f ? lg : 0.2f * lg;
                w_sh[w][lane][h] = __expf(lg * ww);
            }
        }
        __syncwarp();
        int jj = 0;
        for (; jj + 2 <= cnt; jj += 2) {
            int s0 = s_sh[w][jj], s1 = s_sh[w][jj + 1];
            float w0 = w_sh[w][jj][hq], w1 = w_sh[w][jj + 1][hq];
            uint4 v0 = *(const uint4*)&g_h1h[(size_t)s0 * 256 + fcol];
            uint4 v1 = *(const uint4*)&g_h1h[(size_t)s1 * 256 + fcol];
            float2 f;
            f = __half22float2(*(__half2*)&v0.x); acc[0]=fmaf(w0,f.x,acc[0]); acc[1]=fmaf(w0,f.y,acc[1]);
            f = __half22float2(*(__half2*)&v0.y); acc[2]=fmaf(w0,f.x,acc[2]); acc[3]=fmaf(w0,f.y,acc[3]);
            f = __half22float2(*(__half2*)&v0.z); acc[4]=fmaf(w0,f.x,acc[4]); acc[5]=fmaf(w0,f.y,acc[5]);
            f = __half22float2(*(__half2*)&v0.w); acc[6]=fmaf(w0,f.x,acc[6]); acc[7]=fmaf(w0,f.y,acc[7]);
            f = __half22float2(*(__half2*)&v1.x); acc[0]=fmaf(w1,f.x,acc[0]); acc[1]=fmaf(w1,f.y,acc[1]);
            f = __half22float2(*(__half2*)&v1.y); acc[2]=fmaf(w1,f.x,acc[2]); acc[3]=fmaf(w1,f.y,acc[3]);
            f = __half22float2(*(__half2*)&v1.z); acc[4]=fmaf(w1,f.x,acc[4]); acc[5]=fmaf(w1,f.y,acc[5]);
            f = __half22float2(*(__half2*)&v1.w); acc[6]=fmaf(w1,f.x,acc[6]); acc[7]=fmaf(w1,f.y,acc[7]);
            dn += w0 + w1;
        }
        for (; jj < cnt; jj++) {
            int s0 = s_sh[w][jj];
            float w0 = w_sh[w][jj][hq];
            uint4 v0 = *(const uint4*)&g_h1h[(size_t)s0 * 256 + fcol];
            float2 f;
            f = __half22float2(*(__half2*)&v0.x); acc[0]=fmaf(w0,f.x,acc[0]); acc[1]=fmaf(w0,f.y,acc[1]);
            f = __half22float2(*(__half2*)&v0.y); acc[2]=fmaf(w0,f.x,acc[2]); acc[3]=fmaf(w0,f.y,acc[3]);
            f = __half22float2(*(__half2*)&v0.z); acc[4]=fmaf(w0,f.x,acc[4]); acc[5]=fmaf(w0,f.y,acc[5]);
            f = __half22float2(*(__half2*)&v0.w); acc[6]=fmaf(w0,f.x,acc[6]); acc[7]=fmaf(w0,f.y,acc[7]);
            dn += w0;
        }
        __syncwarp();
    }

    float inv = 1.f / (dn + 1e-16f);
    float4 bA = __ldg((const float4*)&b1[fcol]);
    float4 bB = __ldg((const float4*)&b1[fcol + 4]);
    float bb[8] = {bA.x, bA.y, bA.z, bA.w, bB.x, bB.y, bB.z, bB.w};
    __half2 outp[4];
#pragma unroll
    for (int i = 0; i < 4; i++) {
        float o0 = acc[2*i]     * inv + bb[2*i];
        float o1 = acc[2*i + 1] * inv + bb[2*i + 1];
        o0 = o0 > 0.f ? o0 : (__expf(o0) - 1.f);   // ELU
        o1 = o1 > 0.f ? o1 : (__expf(o1) - 1.f);
        outp[i] = __floats2half2_rn(o0, o1);
    }
    *(uint4*)&g_hEh[(size_t)n * 256 + fcol] = *(uint4*)outp;
}

// ------------------------------ GEMM2 (fp16 HMMA) + att2 -------------------
// Block = 128 nodes, 8 warps (warp = 16 rows x 16 cols).  Full W2^T (16x256)
// cp.async'd to smem once; hE streamed in 32-K chunks, double-buffered.
#define B2STR 264             // fp16 elems per B2 row (528B: conflict-free)
#define G2_B  (2 * TILEB)     // after the two A stages
#define G2_SMEM (G2_B + 16 * B2STR * 2)   // 20480 + 8448 = 28928

__global__ void __launch_bounds__(256, 2)
gemm2_mma(const float* __restrict__ attS, const float* __restrict__ attD, int N) {
    extern __shared__ char dsm[];
    uint32_t sb = smem_u32(dsm);
    int tid = threadIdx.x, lane = tid & 31, wid = tid >> 5;
    int row0 = blockIdx.x * 128;

    float acc[2][4];
#pragma unroll
    for (int nt = 0; nt < 2; nt++)
#pragma unroll
        for (int c = 0; c < 4; c++) acc[nt][c] = 0.f;

    int lrow = tid >> 1, lhalf = (tid & 1) * 16;
    const char* a_src = (const char*)&g_hEh[(size_t)(row0 + lrow) * 256 + lhalf];
    uint32_t adoff = (uint32_t)((lrow * ASTR + lhalf) * 2);

    // stage B2 (full 16x256) + A chunk 0; one commit group
    {
        int r = tid >> 4, seg = tid & 15;
        uint32_t bdst = sb + G2_B + (uint32_t)(r * B2STR * 2 + seg * 32);
        const char* bsrc = (const char*)&g_B2f[r * 256 + seg * 16];
        CP16(bdst, bsrc);
        CP16(bdst + 16, bsrc + 16);
    }
    CP16(sb + adoff, a_src);
    CP16(sb + adoff + 16, a_src + 16);
    CP_COMMIT();

    int a_r = wid * 16 + (lane & 15);
    int a_c8 = (lane >> 4) * 8;
    int b_r = lane & 7;
    int b_c8 = ((lane >> 3) & 1) * 8;

    for (int ks = 0; ks < 8; ks++) {
        int stage = ks & 1;
        asm volatile("cp.async.wait_group 0;");
        __syncthreads();
        if (ks < 7) {
            uint32_t nb = sb + (uint32_t)(stage ^ 1) * TILEB;
            CP16(nb + adoff,      a_src + (ks + 1) * 64);
            CP16(nb + adoff + 16, a_src + (ks + 1) * 64 + 16);
            CP_COMMIT();
        }
        uint32_t a_sm = sb + (uint32_t)stage * TILEB;
#pragma unroll
        for (int kk = 0; kk < 2; kk++) {
            int colk = kk * 16;
            int gk = ks * 32 + colk;
            uint32_t bf0, bf1, bg0, bg1;
            ldm_x2(bf0, bf1, sb + G2_B + (uint32_t)((b_r       * B2STR + gk + b_c8) * 2));
            ldm_x2(bg0, bg1, sb + G2_B + (uint32_t)(((b_r + 8) * B2STR + gk + b_c8) * 2));
            uint32_t a0, a1, a2, a3;
            ldm_x4(a0, a1, a2, a3, a_sm + (uint32_t)((a_r * ASTR + colk + a_c8) * 2));
            mma16816f(acc[0], a0, a1, a2, a3, bf0, bf1);
            mma16816f(acc[1], a0, a1, a2, a3, bg0, bg1);
        }
    }

    // --- epilogue: h2 + fused a_s2/a_d2 ---
    int quad = lane >> 2, qt = lane & 3;
    int r_lo = row0 + wid * 16 + quad;
    int r_hi = r_lo + 8;
    float s_lo = 0.f, d_lo = 0.f, s_hi = 0.f, d_hi = 0.f;
#pragma unroll
    for (int nt = 0; nt < 2; nt++) {
        int c = nt * 8 + qt * 2;
        float c0 = acc[nt][0], c1 = acc[nt][1], c2 = acc[nt][2], c3 = acc[nt][3];
        float sA = __ldg(&attS[c]), sB = __ldg(&attS[c + 1]);
        float dA = __ldg(&attD[c]), dB = __ldg(&attD[c + 1]);
        s_lo = fmaf(c0, sA, fmaf(c1, sB, s_lo));
        d_lo = fmaf(c0, dA, fmaf(c1, dB, d_lo));
        s_hi = fmaf(c2, sA, fmaf(c3, sB, s_hi));
        d_hi = fmaf(c2, dA, fmaf(c3, dB, d_hi));
        if (r_lo < N) *(float2*)&g_h2[r_lo * 16 + c] = make_float2(c0, c1);
        if (r_hi < N) *(float2*)&g_h2[r_hi * 16 + c] = make_float2(c2, c3);
    }
#pragma unroll
    for (int off = 2; off > 0; off >>= 1) {
        s_lo += __shfl_xor_sync(0xffffffffu, s_lo, off);
        d_lo += __shfl_xor_sync(0xffffffffu, d_lo, off);
        s_hi += __shfl_xor_sync(0xffffffffu, s_hi, off);
        d_hi += __shfl_xor_sync(0xffffffffu, d_hi, off);
    }
    if (qt == 0) {
        if (r_lo < N) { g_as2[r_lo] = s_lo; g_ad2[r_lo] = d_lo; }
        if (r_hi < N) { g_as2[r_hi] = s_hi; g_ad2[r_hi] = d_hi; }
    }
}

// --------------- agg2 (16 lanes per node) + counter re-zero ----------------
__global__ void agg2_k(const float* __restrict__ b2, float* __restrict__ out, int N) {
    int t = threadIdx.x;
    int lane16 = t & 15;
    int n = blockIdx.x * 16 + (t >> 4);
    if (n >= N) return;
    int deg = min(g_cnt[n], CAP);
    const int2* eb = &g_edge[n * CAP];
    float adv = g_ad2[n];
    float acc[16];
#pragma unroll
    for (int c = 0; c < 16; c++) acc[c] = 0.f;
    float dn = 0.f;
    for (int j = lane16; j < deg; j += 16) {
        int2 e = eb[j];
        int s = e.x;
        float eww = __int_as_float(e.y);
        float lg = g_as2[s] + adv;
        lg = lg > 0.f ? lg : 0.2f * lg;
        float wv = __expf(lg * eww);
        dn += wv;
        const float4* hp = (const float4*)&g_h2[s * 16];
        float4 v0 = hp[0], v1 = hp[1], v2 = hp[2], v3 = hp[3];
        acc[0]  = fmaf(wv, v0.x, acc[0]);  acc[1]  = fmaf(wv, v0.y, acc[1]);
        acc[2]  = fmaf(wv, v0.z, acc[2]);  acc[3]  = fmaf(wv, v0.w, acc[3]);
        acc[4]  = fmaf(wv, v1.x, acc[4]);  acc[5]  = fmaf(wv, v1.y, acc[5]);
        acc[6]  = fmaf(wv, v1.z, acc[6]);  acc[7]  = fmaf(wv, v1.w, acc[7]);
        acc[8]  = fmaf(wv, v2.x, acc[8]);  acc[9]  = fmaf(wv, v2.y, acc[9]);
        acc[10] = fmaf(wv, v2.z, acc[10]); acc[11] = fmaf(wv, v2.w, acc[11]);
        acc[12] = fmaf(wv, v3.x, acc[12]); acc[13] = fmaf(wv, v3.y, acc[13]);
        acc[14] = fmaf(wv, v3.z, acc[14]); acc[15] = fmaf(wv, v3.w, acc[15]);
    }
#pragma unroll
    for (int off = 8; off > 0; off >>= 1) {
        dn += __shfl_xor_sync(0xffffffffu, dn, off);
#pragma unroll
        for (int c = 0; c < 16; c++)
            acc[c] += __shfl_xor_sync(0xffffffffu, acc[c], off);
    }
    if (lane16 == 0) {
        float inv = 1.f / (dn + 1e-16f);
#pragma unroll
        for (int c = 0; c < 16; c++)
            out[(size_t)n * 16 + c] = fmaf(acc[c], inv, b2[c]);
        g_cnt[n] = 0;          // restore invariant for next graph replay
    }
}

// ---------------------------------------------------------------------------
extern "C" void kernel_launch(void* const* d_in, const int* in_sizes, int n_in,
                              void* d_out, int out_size) {
    const float* x     = (const float*)d_in[0];
    const int*   ei    = (const int*)  d_in[1];
    const float* ew    = (const float*)d_in[2];
    const float* W1    = (const float*)d_in[3];
    const float* attS1 = (const float*)d_in[4];
    const float* attD1 = (const float*)d_in[5];
    const float* b1    = (const float*)d_in[6];
    const float* W2    = (const float*)d_in[7];
    const float* attS2 = (const float*)d_in[8];
    const float* attD2 = (const float*)d_in[9];
    const float* b2    = (const float*)d_in[10];
    float* out = (float*)d_out;

    int N  = in_sizes[0] / 256;
    int E  = in_sizes[2];
    int ET = E + N;

    cudaFuncSetAttribute(gemm1_mma, cudaFuncAttributeMaxDynamicSharedMemorySize,
                         G1_SMEM);
    cudaFuncSetAttribute(gemm2_mma, cudaFuncAttributeMaxDynamicSharedMemorySize,
                         G2_SMEM);

    // bucketed edge sort (g_cnt zero at entry) + W1/W2 fp16 fold-in
    int sc_threads = max((ET + 3) / 4, 65536);
    scatter_k<<<(sc_threads + 255) / 256, 256>>>(ei, ew, W1, W2, E, ET);

    // layer 1
    gemm1_mma<<<dim3((N + 127) / 128, 2), 256, G1_SMEM>>>(x, attS1, attD1, N);
    agg1_k<<<(N + 7) / 8, 256>>>(b1, N);

    // layer 2
    gemm2_mma<<<(N + 127) / 128, 256, G2_SMEM>>>(attS2, attD2, N);
    agg2_k<<<(N + 15) / 16, 256>>>(b2, out, N);
}